// round 1
// baseline (speedup 1.0000x reference)
#include <cuda_runtime.h>
#include <cuda_bf16.h>
#include <cstdint>

// Problem constants
#define BB   8
#define NT   2          // edge types
#define NN   2000       // nodes
#define ENN  4000       // NT * NN (state_in/out row count)
#define NNZE 32000      // nnz per (b, type)
#define LL   8
#define DD   64
#define LD   512        // L*D
#define SEG  (BB*NT)    // 16 segments
#define NPB  8          // nodes per block in main kernel
#define KDIM 192        // 3*D
#define ASTR 196        // padded row stride for a-matrix in smem
#define RSTR 65         // padded row stride for r*cur in smem

// ---------------- device scratch (no allocation allowed) ----------------
__device__ int   g_count [SEG * NN];
__device__ int   g_cursor[SEG * NN];
__device__ int   g_rowptr[SEG * (NN + 1)];
__device__ float g_ev    [SEG * NNZE];   // reordered edge values
__device__ int   g_ec    [SEG * NNZE];   // reordered edge cols
__device__ __align__(16) float g_Wt[3 * KDIM * DD];   // W transposed: [mat][i][o]

// ---------------- CSR build ----------------
__global__ void k_zero_counts() {
    int i = blockIdx.x * blockDim.x + threadIdx.x;
    if (i < SEG * NN) g_count[i] = 0;
}

__global__ void k_hist(const int* __restrict__ rows) {
    int idx = blockIdx.x * blockDim.x + threadIdx.x;
    if (idx >= SEG * NNZE) return;
    int seg = idx / NNZE;
    int r   = rows[idx];
    atomicAdd(&g_count[seg * NN + r], 1);
}

__global__ void k_scan() {
    int seg = blockIdx.x;
    int t   = threadIdx.x;
    __shared__ int sm2[256];
    int c[8];
    int ts = 0;
    int base = seg * NN;
#pragma unroll
    for (int j = 0; j < 8; ++j) {
        int idx = t * 8 + j;
        c[j] = (idx < NN) ? g_count[base + idx] : 0;
        ts += c[j];
    }
    sm2[t] = ts;
    __syncthreads();
    for (int off = 1; off < 256; off <<= 1) {
        int v = sm2[t];
        if (t >= off) v += sm2[t - off];
        __syncthreads();
        sm2[t] = v;
        __syncthreads();
    }
    int run = sm2[t] - ts;   // exclusive prefix
#pragma unroll
    for (int j = 0; j < 8; ++j) {
        int idx = t * 8 + j;
        if (idx < NN) {
            g_rowptr[seg * (NN + 1) + idx] = run;
            g_cursor[base + idx] = run;
            run += c[j];
        }
    }
    if (t == 255) g_rowptr[seg * (NN + 1) + NN] = sm2[255];
}

__global__ void k_scatter(const float* __restrict__ vals,
                          const int*   __restrict__ rows,
                          const int*   __restrict__ cols) {
    int idx = blockIdx.x * blockDim.x + threadIdx.x;
    if (idx >= SEG * NNZE) return;
    int seg = idx / NNZE;
    int r   = rows[idx];
    int pos = atomicAdd(&g_cursor[seg * NN + r], 1);
    g_ev[seg * NNZE + pos] = vals[idx];
    g_ec[seg * NNZE + pos] = cols[idx];
}

// ---------------- W transpose: W[mat][o][i] -> Wt[mat][i][o] ----------------
__global__ void k_wt(const float* __restrict__ Wr,
                     const float* __restrict__ Wz,
                     const float* __restrict__ Wh) {
    int idx = blockIdx.x * blockDim.x + threadIdx.x;   // over 3*192*64, write-coalesced
    if (idx >= 3 * KDIM * DD) return;
    int mat = idx / (KDIM * DD);
    int r   = idx - mat * (KDIM * DD);
    int i   = r / DD;
    int o   = r - i * DD;
    const float* W = (mat == 0) ? Wr : (mat == 1) ? Wz : Wh;
    g_Wt[idx] = W[o * KDIM + i];
}

// ---------------- fused SpMM + GEMM + GRU ----------------
__device__ __forceinline__ float sigm(float x) {
    return 1.0f / (1.0f + __expf(-x));
}

__global__ void __launch_bounds__(256)
k_main(const float* __restrict__ state_in,
       const float* __restrict__ state_out,
       const float* __restrict__ state_cur,
       const float* __restrict__ b_r,
       const float* __restrict__ b_z,
       const float* __restrict__ b_h,
       float* __restrict__ out) {
    extern __shared__ float smem[];
    float* As = smem;                 // [64][ASTR]  rows m = node*8 + l; cols: 0:64 a_in, 64:128 a_out, 128:192 cur
    float* RC = smem + 64 * ASTR;     // [64][RSTR]  r * state_cur

    const int blk  = blockIdx.x;
    const int b    = blk / (NN / NPB);
    const int nb   = (blk - b * (NN / NPB)) * NPB;
    const int tid  = threadIdx.x;
    const int w    = tid >> 5;
    const int lane = tid & 31;

    // ---------- Phase 1: SpMM gather into smem ----------
    for (int task = w; task < 16; task += 8) {
        const int node = task >> 1;
        const int type = task & 1;
        const int n    = nb + node;
        const int seg  = b * NT + type;
        const int start = g_rowptr[seg * (NN + 1) + n];
        const int end   = g_rowptr[seg * (NN + 1) + n + 1];
        const float* S  = (type == 0 ? state_in : state_out) + (size_t)b * ENN * LD;

        float4 a0 = {0,0,0,0}, a1 = {0,0,0,0}, a2 = {0,0,0,0}, a3 = {0,0,0,0};
        int   k = start;
        float v = 0.0f;
        int   c = 0;
        if (k < end) { v = g_ev[seg * NNZE + k]; c = g_ec[seg * NNZE + k]; }
        for (; k < end; ++k) {
            const float cv = v;
            const int   cc = c;
            if (k + 1 < end) {
                v = g_ev[seg * NNZE + k + 1];
                c = g_ec[seg * NNZE + k + 1];
            }
            const float4* row = reinterpret_cast<const float4*>(S + (size_t)cc * LD);
            float4 r0 = __ldg(row + lane);
            float4 r1 = __ldg(row + 32 + lane);
            float4 r2 = __ldg(row + 64 + lane);
            float4 r3 = __ldg(row + 96 + lane);
            a0.x += cv * r0.x; a0.y += cv * r0.y; a0.z += cv * r0.z; a0.w += cv * r0.w;
            a1.x += cv * r1.x; a1.y += cv * r1.y; a1.z += cv * r1.z; a1.w += cv * r1.w;
            a2.x += cv * r2.x; a2.y += cv * r2.y; a2.z += cv * r2.z; a2.w += cv * r2.w;
            a3.x += cv * r3.x; a3.y += cv * r3.y; a3.z += cv * r3.z; a3.w += cv * r3.w;
        }
        float4 acc[4] = {a0, a1, a2, a3};
#pragma unroll
        for (int j = 0; j < 4; ++j) {
            const int E  = j * 32 + lane;      // float4 index within [L*D/4]
            const int l  = E >> 4;             // 16 float4 per l
            const int d4 = (E & 15) * 4;
            *reinterpret_cast<float4*>(&As[(node * LL + l) * ASTR + type * DD + d4]) = acc[j];
        }
    }
    // state_cur: warp w loads node w
    {
        const int n = nb + w;
        const float4* C = reinterpret_cast<const float4*>(state_cur + (size_t)(b * NN + n) * LD);
#pragma unroll
        for (int j = 0; j < 4; ++j) {
            const int E  = j * 32 + lane;
            const int l  = E >> 4;
            const int d4 = (E & 15) * 4;
            *reinterpret_cast<float4*>(&As[(w * LL + l) * ASTR + 128 + d4]) = __ldg(C + E);
        }
    }
    __syncthreads();

    // ---------- Phase 2: r,z GEMMs (4m x 4o tile per thread) ----------
    const int og = tid & 15;
    const int mg = tid >> 4;
    const int ob = og * 4;
    const int mb = mg * 4;

    const float* Wr = g_Wt;
    const float* Wz = g_Wt + KDIM * DD;
    const float* Wh = g_Wt + 2 * KDIM * DD;

    float ra[16], za[16];
#pragma unroll
    for (int q = 0; q < 16; ++q) { ra[q] = 0.0f; za[q] = 0.0f; }

#pragma unroll 4
    for (int i = 0; i < KDIM; ++i) {
        const float4 wr = __ldg(reinterpret_cast<const float4*>(Wr + i * DD + ob));
        const float4 wz = __ldg(reinterpret_cast<const float4*>(Wz + i * DD + ob));
        float av[4];
#pragma unroll
        for (int jm = 0; jm < 4; ++jm) av[jm] = As[(mb + jm) * ASTR + i];
#pragma unroll
        for (int jm = 0; jm < 4; ++jm) {
            ra[jm * 4 + 0] += av[jm] * wr.x;
            ra[jm * 4 + 1] += av[jm] * wr.y;
            ra[jm * 4 + 2] += av[jm] * wr.z;
            ra[jm * 4 + 3] += av[jm] * wr.w;
            za[jm * 4 + 0] += av[jm] * wz.x;
            za[jm * 4 + 1] += av[jm] * wz.y;
            za[jm * 4 + 2] += av[jm] * wz.z;
            za[jm * 4 + 3] += av[jm] * wz.w;
        }
    }

    float zz[16];
#pragma unroll
    for (int jm = 0; jm < 4; ++jm) {
        const int m = mb + jm;
#pragma unroll
        for (int jo = 0; jo < 4; ++jo) {
            const int o  = ob + jo;
            const float rv = sigm(ra[jm * 4 + jo] + __ldg(&b_r[o]));
            zz[jm * 4 + jo] = sigm(za[jm * 4 + jo] + __ldg(&b_z[o]));
            RC[m * RSTR + o] = rv * As[m * ASTR + 128 + o];
        }
    }
    __syncthreads();

    // ---------- Phase 3: h GEMM ----------
    float ha[16];
#pragma unroll
    for (int q = 0; q < 16; ++q) ha[q] = 0.0f;

#pragma unroll 4
    for (int i = 0; i < 128; ++i) {
        const float4 wh = __ldg(reinterpret_cast<const float4*>(Wh + i * DD + ob));
        float av[4];
#pragma unroll
        for (int jm = 0; jm < 4; ++jm) av[jm] = As[(mb + jm) * ASTR + i];
#pragma unroll
        for (int jm = 0; jm < 4; ++jm) {
            ha[jm * 4 + 0] += av[jm] * wh.x;
            ha[jm * 4 + 1] += av[jm] * wh.y;
            ha[jm * 4 + 2] += av[jm] * wh.z;
            ha[jm * 4 + 3] += av[jm] * wh.w;
        }
    }
#pragma unroll 4
    for (int i = 128; i < KDIM; ++i) {
        const float4 wh = __ldg(reinterpret_cast<const float4*>(Wh + i * DD + ob));
        float av[4];
#pragma unroll
        for (int jm = 0; jm < 4; ++jm) av[jm] = RC[(mb + jm) * RSTR + (i - 128)];
#pragma unroll
        for (int jm = 0; jm < 4; ++jm) {
            ha[jm * 4 + 0] += av[jm] * wh.x;
            ha[jm * 4 + 1] += av[jm] * wh.y;
            ha[jm * 4 + 2] += av[jm] * wh.z;
            ha[jm * 4 + 3] += av[jm] * wh.w;
        }
    }

    // ---------- Epilogue: GRU combine + store ----------
#pragma unroll
    for (int jm = 0; jm < 4; ++jm) {
        const int m    = mb + jm;
        const int node = m >> 3;
        const int l    = m & 7;
        const int gn   = nb + node;
        float4 o4;
        float tmp[4];
#pragma unroll
        for (int jo = 0; jo < 4; ++jo) {
            const int o   = ob + jo;
            const float h = tanhf(ha[jm * 4 + jo] + __ldg(&b_h[o]));
            const float z = zz[jm * 4 + jo];
            const float cur = As[m * ASTR + 128 + o];
            tmp[jo] = (1.0f - z) * cur + z * h;
        }
        o4.x = tmp[0]; o4.y = tmp[1]; o4.z = tmp[2]; o4.w = tmp[3];
        float* dst = out + ((size_t)(b * NN + gn) * LL + l) * DD + ob;
        *reinterpret_cast<float4*>(dst) = o4;
    }
}

// ---------------- launch ----------------
extern "C" void kernel_launch(void* const* d_in, const int* in_sizes, int n_in,
                              void* d_out, int out_size) {
    (void)in_sizes; (void)n_in; (void)out_size;
    const float* state_in  = (const float*)d_in[0];
    const float* state_out = (const float*)d_in[1];
    const float* state_cur = (const float*)d_in[2];
    const float* A_vals    = (const float*)d_in[3];
    const int*   A_rows    = (const int*)  d_in[4];
    const int*   A_cols    = (const int*)  d_in[5];
    const float* W_r       = (const float*)d_in[6];
    const float* b_r       = (const float*)d_in[7];
    const float* W_z       = (const float*)d_in[8];
    const float* b_z       = (const float*)d_in[9];
    const float* W_h       = (const float*)d_in[10];
    const float* b_h       = (const float*)d_in[11];
    float* out = (float*)d_out;

    const int smem_bytes = (64 * ASTR + 64 * RSTR) * sizeof(float);
    cudaFuncSetAttribute(k_main, cudaFuncAttributeMaxDynamicSharedMemorySize, smem_bytes);

    k_zero_counts<<<(SEG * NN + 255) / 256, 256>>>();
    k_hist<<<(SEG * NNZE + 255) / 256, 256>>>(A_rows);
    k_scan<<<SEG, 256>>>();
    k_scatter<<<(SEG * NNZE + 255) / 256, 256>>>(A_vals, A_rows, A_cols);
    k_wt<<<(3 * KDIM * DD + 255) / 256, 256>>>(W_r, W_z, W_h);
    k_main<<<BB * (NN / NPB), 256, smem_bytes>>>(state_in, state_out, state_cur,
                                                 b_r, b_z, b_h, out);
}